// round 11
// baseline (speedup 1.0000x reference)
#include <cuda_runtime.h>
#include <cstdint>

// ---------------------------------------------------------------------------
// GraphDeConvolution: out_b = relu(A_sparse @ (X_b @ W) + bias), b in {ori,aug}
// Inputs (metadata order):
//   0: feature_ori f32 [50000*512]
//   1: feature_aug f32 [50000*512]
//   2: edge_row    i32 [800000]
//   3: edge_col    i32 [800000]
//   4: edge_val    f32 [800000]
//   5: weight      f32 [512*256]
//   6: bias        f32 [256]
// Output: f32 [2*50000*256]  ( [out_ori | out_aug] )
// ---------------------------------------------------------------------------

#define N_NODES 50000
#define N_EDGES 800000
#define D_IN    512
#define D_OUT   256
#define NF      (N_NODES * D_OUT)

// Scratch (allocation-free rule: __device__ globals)
__device__ float g_sup0[NF];            // support_ori = X_ori @ W
__device__ float g_sup1[NF];            // support_aug = X_aug @ W
__device__ int   g_rowptr[N_NODES + 1];
__device__ int   g_cursor[N_NODES];
__device__ int   g_counts[N_NODES];
__device__ int   g_bcol[N_EDGES];       // CSR-ordered edge cols
__device__ float g_bval[N_EDGES];       // CSR-ordered edge vals

// ---------------------------------------------------------------------------
// CSR build
// ---------------------------------------------------------------------------
__global__ void zero_counts_kernel() {
    int i = blockIdx.x * blockDim.x + threadIdx.x;
    if (i < N_NODES) g_counts[i] = 0;
}

__global__ void hist_kernel(const int* __restrict__ erow) {
    int e = blockIdx.x * blockDim.x + threadIdx.x;
    if (e < N_EDGES) atomicAdd(&g_counts[erow[e]], 1);
}

// Single-block scan over 50000 counts -> rowptr (exclusive in rowptr[0..N]),
// also initializes cursor[i] = rowptr[i].
__global__ void scan_kernel() {
    __shared__ int s[1024];
    int carry = 0;
    if (threadIdx.x == 0) g_rowptr[0] = 0;
    for (int base = 0; base < N_NODES; base += 1024) {
        int i = base + threadIdx.x;
        int v = (i < N_NODES) ? g_counts[i] : 0;
        s[threadIdx.x] = v;
        __syncthreads();
        #pragma unroll
        for (int off = 1; off < 1024; off <<= 1) {
            int t = 0;
            if (threadIdx.x >= off) t = s[threadIdx.x - off];
            __syncthreads();
            if (threadIdx.x >= off) s[threadIdx.x] += t;
            __syncthreads();
        }
        if (i < N_NODES) {
            int incl = s[threadIdx.x];
            g_rowptr[i + 1] = carry + incl;
            g_cursor[i]     = carry + incl - v;   // exclusive prefix
        }
        carry += s[1023];
        __syncthreads();
    }
}

__global__ void bucket_kernel(const int* __restrict__ erow,
                              const int* __restrict__ ecol,
                              const float* __restrict__ eval) {
    int e = blockIdx.x * blockDim.x + threadIdx.x;
    if (e < N_EDGES) {
        int pos = atomicAdd(&g_cursor[erow[e]], 1);
        g_bcol[pos] = ecol[e];
        g_bval[pos] = eval[e];
    }
}

// ---------------------------------------------------------------------------
// TF32 mma.sync GEMM: support[b] = X[b] @ W   (M=50000, K=512, N=256)
// Block tile 128x64, BK=32, 8 warps, warp tile 32x32 (2x m16 by 4x n8)
// ---------------------------------------------------------------------------
__device__ __forceinline__ unsigned f2tf32(float x) {
    unsigned r;
    asm("cvt.rna.tf32.f32 %0, %1;" : "=r"(r) : "f"(x));
    return r;
}

__device__ __forceinline__ void mma_tf32(float c[4], const unsigned a[4],
                                         const unsigned b[2]) {
    asm volatile(
        "mma.sync.aligned.m16n8k8.row.col.f32.tf32.tf32.f32 "
        "{%0,%1,%2,%3}, {%4,%5,%6,%7}, {%8,%9}, {%0,%1,%2,%3};\n"
        : "+f"(c[0]), "+f"(c[1]), "+f"(c[2]), "+f"(c[3])
        : "r"(a[0]), "r"(a[1]), "r"(a[2]), "r"(a[3]),
          "r"(b[0]), "r"(b[1]));
}

#define BM 128
#define BN 64
#define BK 32
#define A_STRIDE 36   // 32 + 4 pad: frag loads map bank = lane (conflict-free)
#define B_STRIDE 68   // 64 + 4 pad: frag loads are a lane permutation

__global__ __launch_bounds__(256) void gemm_tf32_kernel(
    const float* __restrict__ x0, const float* __restrict__ x1,
    const float* __restrict__ w) {
    const float* X  = (blockIdx.z == 0) ? x0 : x1;
    float*      out = (blockIdx.z == 0) ? g_sup0 : g_sup1;
    const int m0 = blockIdx.x * BM;
    const int n0 = blockIdx.y * BN;

    __shared__ unsigned As[BM][A_STRIDE];
    __shared__ unsigned Bs[BK][B_STRIDE];

    const int lane = threadIdx.x & 31;
    const int wid  = threadIdx.x >> 5;
    const int wm   = (wid & 3) * 32;   // warp m-offset within block tile
    const int wn   = (wid >> 2) * 32;  // warp n-offset
    const int gid  = lane >> 2;        // 0..7
    const int ctg  = lane & 3;         // 0..3

    float c[2][4][4];
    #pragma unroll
    for (int mt = 0; mt < 2; mt++)
        #pragma unroll
        for (int nt = 0; nt < 4; nt++)
            #pragma unroll
            for (int k = 0; k < 4; k++) c[mt][nt][k] = 0.f;

    for (int k0 = 0; k0 < D_IN; k0 += BK) {
        // Load A tile 128x32 (4 float4 per thread), convert rna->tf32
        #pragma unroll
        for (int i = 0; i < 4; i++) {
            int idx = threadIdx.x + i * 256;
            int r   = idx >> 3;
            int cc  = (idx & 7) * 4;
            float4 v = make_float4(0.f, 0.f, 0.f, 0.f);
            if (m0 + r < N_NODES)
                v = *(const float4*)(X + (size_t)(m0 + r) * D_IN + k0 + cc);
            As[r][cc + 0] = f2tf32(v.x);
            As[r][cc + 1] = f2tf32(v.y);
            As[r][cc + 2] = f2tf32(v.z);
            As[r][cc + 3] = f2tf32(v.w);
        }
        // Load B tile 32x64 (2 float4 per thread)
        #pragma unroll
        for (int i = 0; i < 2; i++) {
            int idx = threadIdx.x + i * 256;
            int r   = idx >> 4;
            int cc  = (idx & 15) * 4;
            float4 v = *(const float4*)(w + (size_t)(k0 + r) * D_OUT + n0 + cc);
            Bs[r][cc + 0] = f2tf32(v.x);
            Bs[r][cc + 1] = f2tf32(v.y);
            Bs[r][cc + 2] = f2tf32(v.z);
            Bs[r][cc + 3] = f2tf32(v.w);
        }
        __syncthreads();

        #pragma unroll
        for (int ks = 0; ks < 4; ks++) {
            unsigned a[2][4], b[4][2];
            int kk = ks * 8 + ctg;
            #pragma unroll
            for (int mt = 0; mt < 2; mt++) {
                int r = wm + mt * 16 + gid;
                a[mt][0] = As[r][kk];
                a[mt][1] = As[r + 8][kk];
                a[mt][2] = As[r][kk + 4];
                a[mt][3] = As[r + 8][kk + 4];
            }
            #pragma unroll
            for (int nt = 0; nt < 4; nt++) {
                int nn = wn + nt * 8 + gid;
                b[nt][0] = Bs[kk][nn];
                b[nt][1] = Bs[kk + 4][nn];
            }
            #pragma unroll
            for (int mt = 0; mt < 2; mt++)
                #pragma unroll
                for (int nt = 0; nt < 4; nt++)
                    mma_tf32(c[mt][nt], a[mt], b[nt]);
        }
        __syncthreads();
    }

    // Epilogue: fp32 support
    #pragma unroll
    for (int mt = 0; mt < 2; mt++) {
        #pragma unroll
        for (int nt = 0; nt < 4; nt++) {
            int r  = m0 + wm + mt * 16 + gid;
            int cc = n0 + wn + nt * 8 + ctg * 2;
            if (r < N_NODES) {
                out[(size_t)r * D_OUT + cc]     = c[mt][nt][0];
                out[(size_t)r * D_OUT + cc + 1] = c[mt][nt][1];
            }
            if (r + 8 < N_NODES) {
                out[(size_t)(r + 8) * D_OUT + cc]     = c[mt][nt][2];
                out[(size_t)(r + 8) * D_OUT + cc + 1] = c[mt][nt][3];
            }
        }
    }
}

// ---------------------------------------------------------------------------
// Per-row aggregation (no float atomics): 64 threads per row, both branches
// per edge (shares col/val loads), fused bias + relu + store to d_out.
// ---------------------------------------------------------------------------
__global__ __launch_bounds__(256) void aggregate_kernel(
    const float* __restrict__ bias, float* __restrict__ out) {
    int row = blockIdx.x * 4 + (threadIdx.x >> 6);
    if (row >= N_NODES) return;
    int d4 = threadIdx.x & 63;  // float4 lane: dims [d4*4, d4*4+4)

    int start = g_rowptr[row];
    int end   = g_rowptr[row + 1];

    const float4* s0 = reinterpret_cast<const float4*>(g_sup0);
    const float4* s1 = reinterpret_cast<const float4*>(g_sup1);

    float4 acc0 = make_float4(0.f, 0.f, 0.f, 0.f);
    float4 acc1 = make_float4(0.f, 0.f, 0.f, 0.f);

    #pragma unroll 4
    for (int e = start; e < end; e++) {
        int   col = g_bcol[e];
        float val = g_bval[e];
        float4 v0 = s0[(size_t)col * 64 + d4];
        float4 v1 = s1[(size_t)col * 64 + d4];
        acc0.x += val * v0.x; acc0.y += val * v0.y;
        acc0.z += val * v0.z; acc0.w += val * v0.w;
        acc1.x += val * v1.x; acc1.y += val * v1.y;
        acc1.z += val * v1.z; acc1.w += val * v1.w;
    }

    float4 b = reinterpret_cast<const float4*>(bias)[d4];
    float4 r0, r1;
    r0.x = fmaxf(acc0.x + b.x, 0.f); r0.y = fmaxf(acc0.y + b.y, 0.f);
    r0.z = fmaxf(acc0.z + b.z, 0.f); r0.w = fmaxf(acc0.w + b.w, 0.f);
    r1.x = fmaxf(acc1.x + b.x, 0.f); r1.y = fmaxf(acc1.y + b.y, 0.f);
    r1.z = fmaxf(acc1.z + b.z, 0.f); r1.w = fmaxf(acc1.w + b.w, 0.f);

    reinterpret_cast<float4*>(out + (size_t)row * D_OUT)[d4] = r0;
    reinterpret_cast<float4*>(out + (size_t)NF + (size_t)row * D_OUT)[d4] = r1;
}

// ---------------------------------------------------------------------------
extern "C" void kernel_launch(void* const* d_in, const int* in_sizes, int n_in,
                              void* d_out, int out_size) {
    const float* f_ori  = (const float*)d_in[0];
    const float* f_aug  = (const float*)d_in[1];
    const int*   erow   = (const int*)d_in[2];
    const int*   ecol   = (const int*)d_in[3];
    const float* eval   = (const float*)d_in[4];
    const float* weight = (const float*)d_in[5];
    const float* bias   = (const float*)d_in[6];
    float*       out    = (float*)d_out;

    // CSR build (int atomics only)
    zero_counts_kernel<<<(N_NODES + 255) / 256, 256>>>();
    hist_kernel<<<(N_EDGES + 255) / 256, 256>>>(erow);
    scan_kernel<<<1, 1024>>>();
    bucket_kernel<<<(N_EDGES + 255) / 256, 256>>>(erow, ecol, eval);

    // support[b] = X[b] @ W  (tf32 tensor cores, fp32 accumulate)
    dim3 ggrid((N_NODES + BM - 1) / BM, D_OUT / BN, 2);
    gemm_tf32_kernel<<<ggrid, 256>>>(f_ori, f_aug, weight);

    // out[b] = relu(A @ support[b] + bias)
    aggregate_kernel<<<(N_NODES + 3) / 4, 256>>>(bias, out);
}

// round 12
// speedup vs baseline: 1.0028x; 1.0028x over previous
#include <cuda_runtime.h>
#include <cstdint>

// ---------------------------------------------------------------------------
// GraphDeConvolution: out_b = relu(A_sparse @ (X_b @ W) + bias), b in {ori,aug}
// Inputs (metadata order):
//   0: feature_ori f32 [50000*512]
//   1: feature_aug f32 [50000*512]
//   2: edge_row    i32 [800000]
//   3: edge_col    i32 [800000]
//   4: edge_val    f32 [800000]
//   5: weight      f32 [512*256]
//   6: bias        f32 [256]
// Output: f32 [2*50000*256]  ( [out_ori | out_aug] )
// ---------------------------------------------------------------------------

#define N_NODES 50000
#define N_EDGES 800000
#define D_IN    512
#define D_OUT   256
#define NF      (N_NODES * D_OUT)

// Scratch (allocation-free rule: __device__ globals)
__device__ float g_sup0[NF];            // support_ori = X_ori @ W
__device__ float g_sup1[NF];            // support_aug = X_aug @ W
__device__ int   g_rowptr[N_NODES + 1];
__device__ int   g_cursor[N_NODES];
__device__ int   g_counts[N_NODES];
__device__ int   g_bcol[N_EDGES];       // CSR-ordered edge cols
__device__ float g_bval[N_EDGES];       // CSR-ordered edge vals

// ---------------------------------------------------------------------------
// CSR build
// ---------------------------------------------------------------------------
__global__ void zero_counts_kernel() {
    int i = blockIdx.x * blockDim.x + threadIdx.x;
    if (i < N_NODES) g_counts[i] = 0;
}

__global__ void hist_kernel(const int* __restrict__ erow) {
    int e = blockIdx.x * blockDim.x + threadIdx.x;
    if (e < N_EDGES) atomicAdd(&g_counts[erow[e]], 1);
}

// Single-block scan over 50000 counts -> rowptr (exclusive in rowptr[0..N]),
// also initializes cursor[i] = rowptr[i].
__global__ void scan_kernel() {
    __shared__ int s[1024];
    int carry = 0;
    if (threadIdx.x == 0) g_rowptr[0] = 0;
    for (int base = 0; base < N_NODES; base += 1024) {
        int i = base + threadIdx.x;
        int v = (i < N_NODES) ? g_counts[i] : 0;
        s[threadIdx.x] = v;
        __syncthreads();
        #pragma unroll
        for (int off = 1; off < 1024; off <<= 1) {
            int t = 0;
            if (threadIdx.x >= off) t = s[threadIdx.x - off];
            __syncthreads();
            if (threadIdx.x >= off) s[threadIdx.x] += t;
            __syncthreads();
        }
        if (i < N_NODES) {
            int incl = s[threadIdx.x];
            g_rowptr[i + 1] = carry + incl;
            g_cursor[i]     = carry + incl - v;   // exclusive prefix
        }
        carry += s[1023];
        __syncthreads();
    }
}

__global__ void bucket_kernel(const int* __restrict__ erow,
                              const int* __restrict__ ecol,
                              const float* __restrict__ eval) {
    int e = blockIdx.x * blockDim.x + threadIdx.x;
    if (e < N_EDGES) {
        int pos = atomicAdd(&g_cursor[erow[e]], 1);
        g_bcol[pos] = ecol[e];
        g_bval[pos] = eval[e];
    }
}

// ---------------------------------------------------------------------------
// TF32 mma.sync GEMM: support[b] = X[b] @ W   (M=50000, K=512, N=256)
// Block tile 128x64, BK=32, 8 warps, warp tile 32x32 (2x m16 by 4x n8)
// ---------------------------------------------------------------------------
__device__ __forceinline__ unsigned f2tf32(float x) {
    unsigned r;
    asm("cvt.rna.tf32.f32 %0, %1;" : "=r"(r) : "f"(x));
    return r;
}

__device__ __forceinline__ void mma_tf32(float c[4], const unsigned a[4],
                                         const unsigned b[2]) {
    asm volatile(
        "mma.sync.aligned.m16n8k8.row.col.f32.tf32.tf32.f32 "
        "{%0,%1,%2,%3}, {%4,%5,%6,%7}, {%8,%9}, {%0,%1,%2,%3};\n"
        : "+f"(c[0]), "+f"(c[1]), "+f"(c[2]), "+f"(c[3])
        : "r"(a[0]), "r"(a[1]), "r"(a[2]), "r"(a[3]),
          "r"(b[0]), "r"(b[1]));
}

#define BM 128
#define BN 64
#define BK 32
#define A_STRIDE 36   // 32 + 4 pad: frag loads map bank = lane (conflict-free)
#define B_STRIDE 68   // 64 + 4 pad: frag loads are a lane permutation

__global__ __launch_bounds__(256) void gemm_tf32_kernel(
    const float* __restrict__ x0, const float* __restrict__ x1,
    const float* __restrict__ w) {
    const float* X  = (blockIdx.z == 0) ? x0 : x1;
    float*      out = (blockIdx.z == 0) ? g_sup0 : g_sup1;
    const int m0 = blockIdx.x * BM;
    const int n0 = blockIdx.y * BN;

    __shared__ unsigned As[BM][A_STRIDE];
    __shared__ unsigned Bs[BK][B_STRIDE];

    const int lane = threadIdx.x & 31;
    const int wid  = threadIdx.x >> 5;
    const int wm   = (wid & 3) * 32;   // warp m-offset within block tile
    const int wn   = (wid >> 2) * 32;  // warp n-offset
    const int gid  = lane >> 2;        // 0..7
    const int ctg  = lane & 3;         // 0..3

    float c[2][4][4];
    #pragma unroll
    for (int mt = 0; mt < 2; mt++)
        #pragma unroll
        for (int nt = 0; nt < 4; nt++)
            #pragma unroll
            for (int k = 0; k < 4; k++) c[mt][nt][k] = 0.f;

    for (int k0 = 0; k0 < D_IN; k0 += BK) {
        // Load A tile 128x32 (4 float4 per thread), convert rna->tf32
        #pragma unroll
        for (int i = 0; i < 4; i++) {
            int idx = threadIdx.x + i * 256;
            int r   = idx >> 3;
            int cc  = (idx & 7) * 4;
            float4 v = make_float4(0.f, 0.f, 0.f, 0.f);
            if (m0 + r < N_NODES)
                v = *(const float4*)(X + (size_t)(m0 + r) * D_IN + k0 + cc);
            As[r][cc + 0] = f2tf32(v.x);
            As[r][cc + 1] = f2tf32(v.y);
            As[r][cc + 2] = f2tf32(v.z);
            As[r][cc + 3] = f2tf32(v.w);
        }
        // Load B tile 32x64 (2 float4 per thread)
        #pragma unroll
        for (int i = 0; i < 2; i++) {
            int idx = threadIdx.x + i * 256;
            int r   = idx >> 4;
            int cc  = (idx & 15) * 4;
            float4 v = *(const float4*)(w + (size_t)(k0 + r) * D_OUT + n0 + cc);
            Bs[r][cc + 0] = f2tf32(v.x);
            Bs[r][cc + 1] = f2tf32(v.y);
            Bs[r][cc + 2] = f2tf32(v.z);
            Bs[r][cc + 3] = f2tf32(v.w);
        }
        __syncthreads();

        #pragma unroll
        for (int ks = 0; ks < 4; ks++) {
            unsigned a[2][4], b[4][2];
            int kk = ks * 8 + ctg;
            #pragma unroll
            for (int mt = 0; mt < 2; mt++) {
                int r = wm + mt * 16 + gid;
                a[mt][0] = As[r][kk];
                a[mt][1] = As[r + 8][kk];
                a[mt][2] = As[r][kk + 4];
                a[mt][3] = As[r + 8][kk + 4];
            }
            #pragma unroll
            for (int nt = 0; nt < 4; nt++) {
                int nn = wn + nt * 8 + gid;
                b[nt][0] = Bs[kk][nn];
                b[nt][1] = Bs[kk + 4][nn];
            }
            #pragma unroll
            for (int mt = 0; mt < 2; mt++)
                #pragma unroll
                for (int nt = 0; nt < 4; nt++)
                    mma_tf32(c[mt][nt], a[mt], b[nt]);
        }
        __syncthreads();
    }

    // Epilogue: fp32 support
    #pragma unroll
    for (int mt = 0; mt < 2; mt++) {
        #pragma unroll
        for (int nt = 0; nt < 4; nt++) {
            int r  = m0 + wm + mt * 16 + gid;
            int cc = n0 + wn + nt * 8 + ctg * 2;
            if (r < N_NODES) {
                out[(size_t)r * D_OUT + cc]     = c[mt][nt][0];
                out[(size_t)r * D_OUT + cc + 1] = c[mt][nt][1];
            }
            if (r + 8 < N_NODES) {
                out[(size_t)(r + 8) * D_OUT + cc]     = c[mt][nt][2];
                out[(size_t)(r + 8) * D_OUT + cc + 1] = c[mt][nt][3];
            }
        }
    }
}

// ---------------------------------------------------------------------------
// Per-row aggregation (no float atomics): 64 threads per row, both branches
// per edge (shares col/val loads), fused bias + relu + store to d_out.
// ---------------------------------------------------------------------------
__global__ __launch_bounds__(256) void aggregate_kernel(
    const float* __restrict__ bias, float* __restrict__ out) {
    int row = blockIdx.x * 4 + (threadIdx.x >> 6);
    if (row >= N_NODES) return;
    int d4 = threadIdx.x & 63;  // float4 lane: dims [d4*4, d4*4+4)

    int start = g_rowptr[row];
    int end   = g_rowptr[row + 1];

    const float4* s0 = reinterpret_cast<const float4*>(g_sup0);
    const float4* s1 = reinterpret_cast<const float4*>(g_sup1);

    float4 acc0 = make_float4(0.f, 0.f, 0.f, 0.f);
    float4 acc1 = make_float4(0.f, 0.f, 0.f, 0.f);

    #pragma unroll 4
    for (int e = start; e < end; e++) {
        int   col = g_bcol[e];
        float val = g_bval[e];
        float4 v0 = s0[(size_t)col * 64 + d4];
        float4 v1 = s1[(size_t)col * 64 + d4];
        acc0.x += val * v0.x; acc0.y += val * v0.y;
        acc0.z += val * v0.z; acc0.w += val * v0.w;
        acc1.x += val * v1.x; acc1.y += val * v1.y;
        acc1.z += val * v1.z; acc1.w += val * v1.w;
    }

    float4 b = reinterpret_cast<const float4*>(bias)[d4];
    float4 r0, r1;
    r0.x = fmaxf(acc0.x + b.x, 0.f); r0.y = fmaxf(acc0.y + b.y, 0.f);
    r0.z = fmaxf(acc0.z + b.z, 0.f); r0.w = fmaxf(acc0.w + b.w, 0.f);
    r1.x = fmaxf(acc1.x + b.x, 0.f); r1.y = fmaxf(acc1.y + b.y, 0.f);
    r1.z = fmaxf(acc1.z + b.z, 0.f); r1.w = fmaxf(acc1.w + b.w, 0.f);

    reinterpret_cast<float4*>(out + (size_t)row * D_OUT)[d4] = r0;
    reinterpret_cast<float4*>(out + (size_t)NF + (size_t)row * D_OUT)[d4] = r1;
}

// ---------------------------------------------------------------------------
extern "C" void kernel_launch(void* const* d_in, const int* in_sizes, int n_in,
                              void* d_out, int out_size) {
    const float* f_ori  = (const float*)d_in[0];
    const float* f_aug  = (const float*)d_in[1];
    const int*   erow   = (const int*)d_in[2];
    const int*   ecol   = (const int*)d_in[3];
    const float* eval   = (const float*)d_in[4];
    const float* weight = (const float*)d_in[5];
    const float* bias   = (const float*)d_in[6];
    float*       out    = (float*)d_out;

    // CSR build (int atomics only)
    zero_counts_kernel<<<(N_NODES + 255) / 256, 256>>>();
    hist_kernel<<<(N_EDGES + 255) / 256, 256>>>(erow);
    scan_kernel<<<1, 1024>>>();
    bucket_kernel<<<(N_EDGES + 255) / 256, 256>>>(erow, ecol, eval);

    // support[b] = X[b] @ W  (tf32 tensor cores, fp32 accumulate)
    dim3 ggrid((N_NODES + BM - 1) / BM, D_OUT / BN, 2);
    gemm_tf32_kernel<<<ggrid, 256>>>(f_ori, f_aug, weight);

    // out[b] = relu(A @ support[b] + bias)
    aggregate_kernel<<<(N_NODES + 3) / 4, 256>>>(bias, out);
}